// round 15
// baseline (speedup 1.0000x reference)
#include <cuda_runtime.h>
#include <cuda_fp16.h>
#include <math.h>
#include <stdint.h>

// Problem constants
#define B_   1024
#define S_   128
#define D_   256
#define H_   2048
#define O_   10
#define V_   10

// Step tiling
#define BM   128
#define BN   128
#define KT   64            // fp16 per K-tile => 128B/row (SW128 atom)
#define NKT  (H_ / KT)     // 32
#define NB   4             // 4-stage cp.async pipeline
#define TILE_BYTES 16384   // 128 rows x 128B

// Scratch
__device__ __half g_h0[B_ * H_];
__device__ __half g_h1[B_ * H_];
__device__ float  g_T [V_ * H_];    // W_hx @ embed[v] + b_hx   (for h0)
__device__ float  g_T2[V_ * H_];    // g_T + b_hh               (for steps)
__device__ __half g_Wh[H_ * H_];    // fp16 W_hh, row-major [h][k]
__device__ unsigned g_cnt[8][16];   // per (j, x) cumulative step counters

// ---------------------------------------------------------------------------
// helpers
// ---------------------------------------------------------------------------
__device__ __forceinline__ uint32_t smem_u32(const void* p) {
    uint32_t a;
    asm("{ .reg .u64 t; cvta.to.shared.u64 t, %1; cvt.u32.u64 %0, t; }" : "=r"(a) : "l"(p));
    return a;
}
#define SWZ128(o) ((o) ^ (((o) >> 3) & 0x70))

#define CP_ASYNC16(dst, src) \
    asm volatile("cp.async.cg.shared.global [%0], [%1], 16;\n" :: "r"(dst), "l"(src))
#define CP_COMMIT() asm volatile("cp.async.commit_group;\n" ::: "memory")
#define CP_WAIT(n)  asm volatile("cp.async.wait_group %0;\n" :: "n"(n) : "memory")

#define LDSM4(R, A)                                                        \
    asm volatile("ldmatrix.sync.aligned.m8n8.x4.shared.b16 "               \
                 "{%0,%1,%2,%3}, [%4];"                                    \
                 : "=r"((R)[0]), "=r"((R)[1]), "=r"((R)[2]), "=r"((R)[3])  \
                 : "r"(A))

__device__ __forceinline__ void mma16816(float* d, const uint32_t* a,
                                         uint32_t b0, uint32_t b1) {
    asm volatile(
        "mma.sync.aligned.m16n8k16.row.col.f32.f16.f16.f32 "
        "{%0,%1,%2,%3}, {%4,%5,%6,%7}, {%8,%9}, {%0,%1,%2,%3};\n"
        : "+f"(d[0]), "+f"(d[1]), "+f"(d[2]), "+f"(d[3])
        : "r"(a[0]), "r"(a[1]), "r"(a[2]), "r"(a[3]), "r"(b0), "r"(b1));
}

// tanh(x) = 1 - 2/(e^{2x}+1) via MUFU ex2 + rcp; rel err ~1e-6.
__device__ __forceinline__ float fast_tanh(float x) {
    float e;
    asm("ex2.approx.f32 %0, %1;" : "=f"(e) : "f"(x * 2.8853900817779268f));
    float r;
    asm("rcp.approx.f32 %0, %1;" : "=f"(r) : "f"(e + 1.0f));
    return fmaf(-2.0f, r, 1.0f);
}

__device__ __forceinline__ void poll_ge(const unsigned* p, unsigned tgt) {
    unsigned v;
    do {
        asm volatile("ld.acquire.gpu.u32 %0, [%1];" : "=r"(v) : "l"(p) : "memory");
    } while (v < tgt);
}

// ---------------------------------------------------------------------------
// Setup kernels
// ---------------------------------------------------------------------------
__global__ void precompute_T_kernel(const float* __restrict__ embed,
                                    const float* __restrict__ W_hx,
                                    const float* __restrict__ b_hx) {
    int h = blockIdx.x * blockDim.x + threadIdx.x;
    int v = blockIdx.y;
    if (h >= H_) return;
    const float4* wr = reinterpret_cast<const float4*>(W_hx + (size_t)h * D_);
    const float4* er = reinterpret_cast<const float4*>(embed + (size_t)v * D_);
    float s = 0.f;
#pragma unroll 8
    for (int i = 0; i < D_ / 4; i++) {
        float4 w = wr[i];
        float4 e = er[i];
        s += w.x * e.x + w.y * e.y + w.z * e.z + w.w * e.w;
    }
    g_T[v * H_ + h] = s + b_hx[h];
}

__global__ void make_T2_kernel(const float* __restrict__ b_hh) {
    int i = blockIdx.x * blockDim.x + threadIdx.x;
    g_T2[i] = g_T[i] + b_hh[i & (H_ - 1)];
}

__global__ void cvt_W_kernel(const float* __restrict__ W) {
    int i = blockIdx.x * blockDim.x + threadIdx.x;
    g_Wh[i] = __float2half(W[i]);
}

// h0 = tanh(T[x[:,0]]) fp16; first 128 threads also reset the flag counters
__global__ void init_h_kernel(const int* __restrict__ x) {
    int idx = blockIdx.x * blockDim.x + threadIdx.x;
    if (idx < 128) ((unsigned*)g_cnt)[idx] = 0u;
    int b = idx >> 11;
    int h = idx & (H_ - 1);
    int tok = x[b * S_];
    g_h0[idx] = __float2half(fast_tanh(g_T[tok * H_ + h]));
}

// ---------------------------------------------------------------------------
// Persistent recurrence kernel. Grid (16,8)=128 CTAs (one wave), 256 threads.
// Per step: 128x128x2048 fp16 HMMA with 4-stage cp.async staging (SW128).
// Cross-step sync: fine-grained per-(j,x) release/acquire counters instead of
// a global grid barrier — k-tile nt only waits for producer x = nt>>1, so the
// pipeline flows across step boundaries.
// ---------------------------------------------------------------------------
__global__ __launch_bounds__(256, 1)
void rnn_persist(const int* __restrict__ x) {
    extern __shared__ char dsm[];
    const uint32_t sraw = smem_u32(dsm);
    const uint32_t smA  = (sraw + 1023) & ~1023u;
    const uint32_t smB  = smA + NB * TILE_BYTES;

    const int tid  = threadIdx.x;
    const int warp = tid >> 5;
    const int lane = tid & 31;
    const int bx   = blockIdx.x;     // N tile index (0..15)
    const int by   = blockIdx.y;     // M tile index (0..7)
    const int bm0  = by * BM;
    const int bn0  = bx * BN;
    const int wm   = warp >> 2;
    const int wn   = warp & 3;

    const unsigned* myrow_cnt = &g_cnt[by][0];

    // ---- loader mapping: 8 x cp.async(16B)/thread: 4 A rows + 4 B rows ----
    const int ch8 = tid & 7;
    const int r0  = tid >> 3;
    size_t aoff[4];
    const char* gB[4];
    uint32_t offR[4];
#pragma unroll
    for (int j = 0; j < 4; j++) {
        int row = r0 + 32 * j;
        aoff[j] = (size_t)(bm0 + row) * (H_ * 2) + ch8 * 16;
        gB[j]   = (const char*)(g_Wh + (size_t)(bn0 + row) * H_) + ch8 * 16;
        offR[j] = SWZ128((uint32_t)(row * 128 + ch8 * 16));
    }

#define LOAD_TILE(ABASE, TT, BUF)                                     \
    do {                                                              \
        size_t _kb = (size_t)(TT) * 128;                              \
        uint32_t _da = smA + (BUF) * TILE_BYTES;                      \
        uint32_t _db = smB + (BUF) * TILE_BYTES;                      \
        CP_ASYNC16(_da + offR[0], (ABASE) + aoff[0] + _kb);           \
        CP_ASYNC16(_da + offR[1], (ABASE) + aoff[1] + _kb);           \
        CP_ASYNC16(_da + offR[2], (ABASE) + aoff[2] + _kb);           \
        CP_ASYNC16(_da + offR[3], (ABASE) + aoff[3] + _kb);           \
        CP_ASYNC16(_db + offR[0], gB[0] + _kb);                       \
        CP_ASYNC16(_db + offR[1], gB[1] + _kb);                       \
        CP_ASYNC16(_db + offR[2], gB[2] + _kb);                       \
        CP_ASYNC16(_db + offR[3], gB[3] + _kb);                       \
        CP_COMMIT();                                                  \
    } while (0)

    // ---- ldmatrix lane addresses (SW128) ----
    uint32_t rA128[4], rA7[4];
    const uint32_t pA = lane >> 4;
#pragma unroll
    for (int f = 0; f < 4; f++) {
        uint32_t r = wm * 64 + f * 16 + (lane & 7) + ((lane >> 3) & 1) * 8;
        rA128[f] = r * 128;
        rA7[f]   = r & 7;
    }
    uint32_t rB128[2], rB7[2];
    const uint32_t pB = (lane >> 3) & 1;
#pragma unroll
    for (int q = 0; q < 2; q++) {
        uint32_t r = wn * 32 + q * 16 + (lane & 7) + ((lane >> 4) & 1) * 8;
        rB128[q] = r * 128;
        rB7[q]   = r & 7;
    }

#define LOAD_FRAGS(DA, DB, SA, SB, S)                                            \
    do {                                                                         \
        _Pragma("unroll")                                                        \
        for (int _f = 0; _f < 4; _f++) {                                         \
            uint32_t _ad = (SA) + rA128[_f] + ((((2u*(S)) + pA) ^ rA7[_f]) << 4);\
            LDSM4((DA)[_f], _ad);                                                \
        }                                                                        \
        _Pragma("unroll")                                                        \
        for (int _q = 0; _q < 2; _q++) {                                         \
            uint32_t _ad = (SB) + rB128[_q] + ((((2u*(S)) + pB) ^ rB7[_q]) << 4);\
            LDSM4((DB)[_q], _ad);                                                \
        }                                                                        \
    } while (0)

    // epilogue constants
    const int erlo = bm0 + wm * 64 + (lane >> 2);    // + f*16
    const int ecol = bn0 + wn * 32 + (lane & 3) * 2; // + n*8

    // ---- prologue for step 1 (flags trivially 0 >= 0; no poll needed) ----
    const char* As = (const char*)g_h0;
    LOAD_TILE(As, 0, 0);
    LOAD_TILE(As, 1, 1);
    LOAD_TILE(As, 2, 2);

    // ---- time loop ----
#pragma unroll 1
    for (int t = 1; t < S_; ++t) {
        const int par = (t - 1) & 1;
        __half* __restrict__ Cg = par ? g_h0 : g_h1;
        const unsigned need = (unsigned)(t - 1);   // producers must have signaled t-1

        float acc[4][4][4];
#pragma unroll
        for (int f = 0; f < 4; f++)
#pragma unroll
            for (int n = 0; n < 4; n++)
#pragma unroll
                for (int k = 0; k < 4; k++) acc[f][n][k] = 0.f;

        uint32_t afr[2][4][4], bfr[2][2][4];

#pragma unroll 1
        for (int it = 0; it < NKT; ++it) {
            if (it < NKT - 2)       { CP_WAIT(2); }
            else if (it == NKT - 2) { CP_WAIT(1); }
            else                    { CP_WAIT(0); }
            // gate the upcoming tile's loads on its specific producer
            const int nt = it + 3;
            if (tid == 0 && nt < NKT && !(nt & 1))
                poll_ge(myrow_cnt + (nt >> 1), need);
            __syncthreads();
            if (nt < NKT) LOAD_TILE(As, nt, nt & 3);

            const uint32_t sa = smA + (it & 3) * TILE_BYTES;
            const uint32_t sb = smB + (it & 3) * TILE_BYTES;

            LOAD_FRAGS(afr[0], bfr[0], sa, sb, 0);
#pragma unroll
            for (int s = 0; s < 4; s++) {
                const int cur = s & 1;
                if (s < 3) LOAD_FRAGS(afr[cur ^ 1], bfr[cur ^ 1], sa, sb, s + 1);
#pragma unroll
                for (int f = 0; f < 4; f++)
#pragma unroll
                    for (int n = 0; n < 4; n++)
                        mma16816(acc[f][n], afr[cur][f],
                                 bfr[cur][n >> 1][(n & 1) * 2],
                                 bfr[cur][n >> 1][(n & 1) * 2 + 1]);
            }
        }

        // ---- fused epilogue: + T2[x[b,t]], tanh, fp16 store ----
#pragma unroll
        for (int f = 0; f < 4; f++) {
            int rlo = erlo + f * 16;
            int rhi = rlo + 8;
            const float* Tlo = g_T2 + x[rlo * S_ + t] * H_;
            const float* Thi = g_T2 + x[rhi * S_ + t] * H_;
#pragma unroll
            for (int n = 0; n < 4; n++) {
                int col = ecol + n * 8;
                float v0 = fast_tanh(acc[f][n][0] + Tlo[col]);
                float v1 = fast_tanh(acc[f][n][1] + Tlo[col + 1]);
                *(__half2*)(Cg + (size_t)rlo * H_ + col) = __floats2half2_rn(v0, v1);
                v0 = fast_tanh(acc[f][n][2] + Thi[col]);
                v1 = fast_tanh(acc[f][n][3] + Thi[col + 1]);
                *(__half2*)(Cg + (size_t)rhi * H_ + col) = __floats2half2_rn(v0, v1);
            }
        }

        // ---- signal own tile done; then gate + issue next step's prologue ----
        if (t < S_ - 1) {
            __syncthreads();                     // all stores of this CTA done
            if (tid == 0) {
                // SIGNAL FIRST (deadlock-free), then poll producers 0 and 1
                asm volatile("red.release.gpu.add.u32 [%0], %1;"
                             :: "l"(&g_cnt[by][bx]), "r"(1u) : "memory");
                poll_ge(myrow_cnt + 0, (unsigned)t);
                poll_ge(myrow_cnt + 1, (unsigned)t);
            }
            __syncthreads();                     // polls complete before loads

            As = (const char*)Cg;
            LOAD_TILE(As, 0, 0);
            LOAD_TILE(As, 1, 1);
            LOAD_TILE(As, 2, 2);
        }
    }
#undef LOAD_TILE
#undef LOAD_FRAGS
}

// ---------------------------------------------------------------------------
// Output: o = hT @ W_oh^T + b_oh ; softmax over O=10 (h fp16, in g_h1)
// ---------------------------------------------------------------------------
__global__ __launch_bounds__(256)
void output_softmax_kernel(const float* __restrict__ W_oh,
                           const float* __restrict__ b_oh,
                           float* __restrict__ out) {
    const int b = blockIdx.x;
    const int tid = threadIdx.x;
    const __half* hrow = g_h1 + (size_t)b * H_;

    float acc[O_];
#pragma unroll
    for (int j = 0; j < O_; j++) acc[j] = 0.f;

    for (int k = tid; k < H_; k += 256) {
        float hv = __half2float(hrow[k]);
#pragma unroll
        for (int j = 0; j < O_; j++) acc[j] += hv * W_oh[j * H_ + k];
    }
#pragma unroll
    for (int off = 16; off > 0; off >>= 1)
#pragma unroll
        for (int j = 0; j < O_; j++)
            acc[j] += __shfl_down_sync(0xffffffffu, acc[j], off);

    __shared__ float part[8][O_];
    if ((tid & 31) == 0) {
#pragma unroll
        for (int j = 0; j < O_; j++) part[tid >> 5][j] = acc[j];
    }
    __syncthreads();

    if (tid == 0) {
        float o[O_];
#pragma unroll
        for (int j = 0; j < O_; j++) {
            float s = b_oh[j];
#pragma unroll
            for (int w = 0; w < 8; w++) s += part[w][j];
            o[j] = s;
        }
        float m = o[0];
#pragma unroll
        for (int j = 1; j < O_; j++) m = fmaxf(m, o[j]);
        float s = 0.f;
#pragma unroll
        for (int j = 0; j < O_; j++) { o[j] = expf(o[j] - m); s += o[j]; }
        float inv = 1.f / s;
#pragma unroll
        for (int j = 0; j < O_; j++) out[b * O_ + j] = o[j] * inv;
    }
}

// ---------------------------------------------------------------------------
// Launch (graph-capturable; no allocs/syncs).
// Inputs: x, embed, W_hx, b_hx, W_hh, b_hh, W_oh, b_oh
// ---------------------------------------------------------------------------
#define STEP_SMEM (1024 + 2 * NB * TILE_BYTES)

extern "C" void kernel_launch(void* const* d_in, const int* in_sizes, int n_in,
                              void* d_out, int out_size) {
    const int*   x     = (const int*)  d_in[0];
    const float* embed = (const float*)d_in[1];
    const float* W_hx  = (const float*)d_in[2];
    const float* b_hx  = (const float*)d_in[3];
    const float* W_hh  = (const float*)d_in[4];
    const float* b_hh  = (const float*)d_in[5];
    const float* W_oh  = (const float*)d_in[6];
    const float* b_oh  = (const float*)d_in[7];
    float* out = (float*)d_out;

    cudaFuncSetAttribute(rnn_persist,
                         cudaFuncAttributeMaxDynamicSharedMemorySize, STEP_SMEM);

    precompute_T_kernel<<<dim3(H_ / 256, V_), 256>>>(embed, W_hx, b_hx);
    make_T2_kernel<<<(V_ * H_) / 256, 256>>>(b_hh);
    cvt_W_kernel<<<(H_ * H_) / 256, 256>>>(W_hh);
    init_h_kernel<<<(B_ * H_) / 256, 256>>>(x);

    rnn_persist<<<dim3(H_ / BN, B_ / BM), 256, STEP_SMEM>>>(x);   // (16,8)=128 CTAs

    output_softmax_kernel<<<B_, 256>>>(W_oh, b_oh, out);
}

// round 16
// speedup vs baseline: 1.1346x; 1.1346x over previous
#include <cuda_runtime.h>
#include <cuda_fp16.h>
#include <math.h>
#include <stdint.h>

// Problem constants
#define B_   1024
#define S_   128
#define D_   256
#define H_   2048
#define O_   10
#define V_   10

// Step tiling
#define BM   128
#define BN   128
#define KT   64            // fp16 per K-tile => 128B/row (SW128 atom)
#define NKT  (H_ / KT)     // 32
#define NB   4             // 4-stage pipeline
#define TILE_BYTES 16384   // 128 rows x 128B
#define NCONS 256          // 8 consumer warps (2x4 grid, 64x32 warp tile)
#define NPROD 64           // 2 producer warps
#define NTHR  (NCONS + NPROD)

// Scratch
__device__ __half g_h0[B_ * H_];
__device__ __half g_h1[B_ * H_];
__device__ float  g_T [V_ * H_];    // W_hx @ embed[v] + b_hx   (for h0)
__device__ float  g_T2[V_ * H_];    // g_T + b_hh               (for steps)
__device__ __half g_Wh[H_ * H_];    // fp16 W_hh, row-major [h][k]

// ---------------------------------------------------------------------------
// helpers
// ---------------------------------------------------------------------------
__device__ __forceinline__ uint32_t smem_u32(const void* p) {
    uint32_t a;
    asm("{ .reg .u64 t; cvta.to.shared.u64 t, %1; cvt.u32.u64 %0, t; }" : "=r"(a) : "l"(p));
    return a;
}

#define CP_ASYNC16(dst, src) \
    asm volatile("cp.async.cg.shared.global [%0], [%1], 16;\n" :: "r"(dst), "l"(src))
#define CP_COMMIT() asm volatile("cp.async.commit_group;\n" ::: "memory")
#define CP_WAIT(n)  asm volatile("cp.async.wait_group %0;\n" :: "n"(n) : "memory")

// named barriers: full[s] = id s (0..3), empty[s] = id 4+s. count = all 320.
#define BAR_SYNC(id)   asm volatile("bar.sync %0, %1;"   :: "r"(id), "n"(NTHR) : "memory")
#define BAR_ARRIVE(id) asm volatile("bar.arrive %0, %1;" :: "r"(id), "n"(NTHR) : "memory")

#define LDSM4(R, A)                                                        \
    asm volatile("ldmatrix.sync.aligned.m8n8.x4.shared.b16 "               \
                 "{%0,%1,%2,%3}, [%4];"                                    \
                 : "=r"((R)[0]), "=r"((R)[1]), "=r"((R)[2]), "=r"((R)[3])  \
                 : "r"(A))

__device__ __forceinline__ void mma16816(float* d, const uint32_t* a,
                                         uint32_t b0, uint32_t b1) {
    asm volatile(
        "mma.sync.aligned.m16n8k16.row.col.f32.f16.f16.f32 "
        "{%0,%1,%2,%3}, {%4,%5,%6,%7}, {%8,%9}, {%0,%1,%2,%3};\n"
        : "+f"(d[0]), "+f"(d[1]), "+f"(d[2]), "+f"(d[3])
        : "r"(a[0]), "r"(a[1]), "r"(a[2]), "r"(a[3]), "r"(b0), "r"(b1));
}

// tanh(x) = 1 - 2/(e^{2x}+1) via MUFU ex2 + rcp; rel err ~1e-6.
__device__ __forceinline__ float fast_tanh(float x) {
    float e;
    asm("ex2.approx.f32 %0, %1;" : "=f"(e) : "f"(x * 2.8853900817779268f));
    float r;
    asm("rcp.approx.f32 %0, %1;" : "=f"(r) : "f"(e + 1.0f));
    return fmaf(-2.0f, r, 1.0f);
}

// ---------------------------------------------------------------------------
// Setup kernels
// ---------------------------------------------------------------------------
__global__ void precompute_T_kernel(const float* __restrict__ embed,
                                    const float* __restrict__ W_hx,
                                    const float* __restrict__ b_hx) {
    int h = blockIdx.x * blockDim.x + threadIdx.x;
    int v = blockIdx.y;
    if (h >= H_) return;
    const float4* wr = reinterpret_cast<const float4*>(W_hx + (size_t)h * D_);
    const float4* er = reinterpret_cast<const float4*>(embed + (size_t)v * D_);
    float s = 0.f;
#pragma unroll 8
    for (int i = 0; i < D_ / 4; i++) {
        float4 w = wr[i];
        float4 e = er[i];
        s += w.x * e.x + w.y * e.y + w.z * e.z + w.w * e.w;
    }
    g_T[v * H_ + h] = s + b_hx[h];
}

__global__ void make_T2_kernel(const float* __restrict__ b_hh) {
    int i = blockIdx.x * blockDim.x + threadIdx.x;
    g_T2[i] = g_T[i] + b_hh[i & (H_ - 1)];
}

__global__ void cvt_W_kernel(const float* __restrict__ W) {
    int i = blockIdx.x * blockDim.x + threadIdx.x;
    g_Wh[i] = __float2half(W[i]);
}

__global__ void init_h_kernel(const int* __restrict__ x) {
    int idx = blockIdx.x * blockDim.x + threadIdx.x;
    int b = idx >> 11;
    int h = idx & (H_ - 1);
    int tok = x[b * S_];
    g_h0[idx] = __float2half(fast_tanh(g_T[tok * H_ + h]));
}

// ---------------------------------------------------------------------------
// Step kernel: C = fp16(tanh(A @ Wh^T + T2[x[:,t]])), 128x128x2048 per CTA,
// grid (16,8)=128 CTAs, 320 threads: 8 consumer warps (LDSM+MMA) + 2 producer
// warps (cp.async). Stage handoff via named barriers full[s]/empty[s] —
// no __syncthreads in the loop; producer free-runs up to 4 tiles ahead.
// ---------------------------------------------------------------------------
__global__ __launch_bounds__(NTHR, 1)
void rnn_step_ws(int parity,
                 const int* __restrict__ x,
                 int t) {
    const char* __restrict__ Abase = parity ? (const char*)g_h1 : (const char*)g_h0;
    __half*     __restrict__ Cg    = parity ? g_h0 : g_h1;

    extern __shared__ char dsm[];
    const uint32_t sraw = smem_u32(dsm);
    const uint32_t smA  = (sraw + 1023) & ~1023u;
    const uint32_t smB  = smA + NB * TILE_BYTES;

    const int tid  = threadIdx.x;
    const int warp = tid >> 5;
    const int lane = tid & 31;
    const int bm0  = blockIdx.y * BM;
    const int bn0  = blockIdx.x * BN;

    if (warp >= 8) {
        // ===================== PRODUCER (2 warps, 64 threads) ===============
        const int ptid = tid - NCONS;        // 0..63
        const int ch8  = ptid & 7;           // 16B chunk in 128B row
        const int r0   = ptid >> 3;          // 0..7 ; rows r0 + 8j, j=0..15
        // swizzled dst offset: row*128 + ((ch8 ^ (row&7))*16); (row&7)==r0 const
        const uint32_t dbase = (uint32_t)r0 * 128u + ((uint32_t)(ch8 ^ r0) << 4);
        const size_t arow0 = (size_t)(bm0 + r0) * (H_ * 2) + ch8 * 16;
        const char*  bsrc0 = (const char*)g_Wh + (size_t)(bn0 + r0) * (H_ * 2) + ch8 * 16;
        const size_t rstep = (size_t)8 * (H_ * 2);   // 8-row stride in bytes

#define LOAD_TILE(NT)                                                      \
    do {                                                                   \
        uint32_t _da = smA + ((NT) & 3) * TILE_BYTES + dbase;              \
        uint32_t _db = smB + ((NT) & 3) * TILE_BYTES + dbase;              \
        size_t _kb = (size_t)(NT) * 128;                                   \
        _Pragma("unroll")                                                  \
        for (int _j = 0; _j < 16; _j++) {                                  \
            CP_ASYNC16(_da + _j * 1024u, Abase + arow0 + _j * rstep + _kb);\
            CP_ASYNC16(_db + _j * 1024u, bsrc0 + _j * rstep + _kb);        \
        }                                                                  \
        CP_COMMIT();                                                       \
    } while (0)

        // prologue: stages 0..2
        LOAD_TILE(0);
        LOAD_TILE(1);
        LOAD_TILE(2);

#pragma unroll 1
        for (int it = 0; it < NKT; ++it) {
            const int nt = it + 3;
            if (nt < NKT) {
                if (nt >= NB) BAR_SYNC(4 + (nt & 3));   // wait stage free
                LOAD_TILE(nt);
            }
            // group for tile 'it' must be complete before signaling full
            if (it < NKT - 3)       { CP_WAIT(3); }
            else if (it == NKT - 3) { CP_WAIT(2); }
            else if (it == NKT - 2) { CP_WAIT(1); }
            else                    { CP_WAIT(0); }
            BAR_ARRIVE(it & 3);                         // full[s]
        }
#undef LOAD_TILE
        return;   // producers done; all barrier arrivals already posted
    }

    // ======================= CONSUMER (8 warps) =============================
    const int wm = warp >> 2;        // 0..1
    const int wn = warp & 3;         // 0..3

    // ldmatrix lane addresses (SW128)
    uint32_t rA128[4], rA7[4];
    const uint32_t pA = lane >> 4;
#pragma unroll
    for (int f = 0; f < 4; f++) {
        uint32_t r = wm * 64 + f * 16 + (lane & 7) + ((lane >> 3) & 1) * 8;
        rA128[f] = r * 128;
        rA7[f]   = r & 7;
    }
    uint32_t rB128[2], rB7[2];
    const uint32_t pB = (lane >> 3) & 1;
#pragma unroll
    for (int q = 0; q < 2; q++) {
        uint32_t r = wn * 32 + q * 16 + (lane & 7) + ((lane >> 4) & 1) * 8;
        rB128[q] = r * 128;
        rB7[q]   = r & 7;
    }

    float acc[4][4][4];
#pragma unroll
    for (int f = 0; f < 4; f++)
#pragma unroll
        for (int n = 0; n < 4; n++)
#pragma unroll
            for (int k = 0; k < 4; k++) acc[f][n][k] = 0.f;

#pragma unroll 1
    for (int it = 0; it < NKT; ++it) {
        BAR_SYNC(it & 3);                                // wait full[s]

        const uint32_t sa = smA + (it & 3) * TILE_BYTES;
        const uint32_t sb = smB + (it & 3) * TILE_BYTES;

#pragma unroll
        for (int s = 0; s < 4; s++) {
            uint32_t afr[4][4], bfr[2][4];
#pragma unroll
            for (int f = 0; f < 4; f++) {
                uint32_t ad = sa + rA128[f] + (((2u * s + pA) ^ rA7[f]) << 4);
                LDSM4(afr[f], ad);
            }
#pragma unroll
            for (int q = 0; q < 2; q++) {
                uint32_t ad = sb + rB128[q] + (((2u * s + pB) ^ rB7[q]) << 4);
                LDSM4(bfr[q], ad);
            }
            if (s == 3) BAR_ARRIVE(4 + (it & 3));        // stage drained
#pragma unroll
            for (int f = 0; f < 4; f++)
#pragma unroll
                for (int n = 0; n < 4; n++)
                    mma16816(acc[f][n], afr[f],
                             bfr[n >> 1][(n & 1) * 2], bfr[n >> 1][(n & 1) * 2 + 1]);
        }
    }

    // ---- fused epilogue: + T2[x[b,t]], tanh, fp16 store ----
    const int erlo = bm0 + wm * 64 + (lane >> 2);
    const int ecol = bn0 + wn * 32 + (lane & 3) * 2;
#pragma unroll
    for (int f = 0; f < 4; f++) {
        int rlo = erlo + f * 16;
        int rhi = rlo + 8;
        const float* Tlo = g_T2 + x[rlo * S_ + t] * H_;
        const float* Thi = g_T2 + x[rhi * S_ + t] * H_;
#pragma unroll
        for (int n = 0; n < 4; n++) {
            int col = ecol + n * 8;
            float v0 = fast_tanh(acc[f][n][0] + Tlo[col]);
            float v1 = fast_tanh(acc[f][n][1] + Tlo[col + 1]);
            *(__half2*)(Cg + (size_t)rlo * H_ + col) = __floats2half2_rn(v0, v1);
            v0 = fast_tanh(acc[f][n][2] + Thi[col]);
            v1 = fast_tanh(acc[f][n][3] + Thi[col + 1]);
            *(__half2*)(Cg + (size_t)rhi * H_ + col) = __floats2half2_rn(v0, v1);
        }
    }
}

// ---------------------------------------------------------------------------
// Output: o = hT @ W_oh^T + b_oh ; softmax over O=10 (h fp16, in g_h1)
// ---------------------------------------------------------------------------
__global__ __launch_bounds__(256)
void output_softmax_kernel(const float* __restrict__ W_oh,
                           const float* __restrict__ b_oh,
                           float* __restrict__ out) {
    const int b = blockIdx.x;
    const int tid = threadIdx.x;
    const __half* hrow = g_h1 + (size_t)b * H_;

    float acc[O_];
#pragma unroll
    for (int j = 0; j < O_; j++) acc[j] = 0.f;

    for (int k = tid; k < H_; k += 256) {
        float hv = __half2float(hrow[k]);
#pragma unroll
        for (int j = 0; j < O_; j++) acc[j] += hv * W_oh[j * H_ + k];
    }
#pragma unroll
    for (int off = 16; off > 0; off >>= 1)
#pragma unroll
        for (int j = 0; j < O_; j++)
            acc[j] += __shfl_down_sync(0xffffffffu, acc[j], off);

    __shared__ float part[8][O_];
    if ((tid & 31) == 0) {
#pragma unroll
        for (int j = 0; j < O_; j++) part[tid >> 5][j] = acc[j];
    }
    __syncthreads();

    if (tid == 0) {
        float o[O_];
#pragma unroll
        for (int j = 0; j < O_; j++) {
            float s = b_oh[j];
#pragma unroll
            for (int w = 0; w < 8; w++) s += part[w][j];
            o[j] = s;
        }
        float m = o[0];
#pragma unroll
        for (int j = 1; j < O_; j++) m = fmaxf(m, o[j]);
        float s = 0.f;
#pragma unroll
        for (int j = 0; j < O_; j++) { o[j] = expf(o[j] - m); s += o[j]; }
        float inv = 1.f / s;
#pragma unroll
        for (int j = 0; j < O_; j++) out[b * O_ + j] = o[j] * inv;
    }
}

// ---------------------------------------------------------------------------
// Launch (graph-capturable; no allocs/syncs).
// Inputs: x, embed, W_hx, b_hx, W_hh, b_hh, W_oh, b_oh
// ---------------------------------------------------------------------------
#define STEP_SMEM (1024 + 2 * NB * TILE_BYTES)

extern "C" void kernel_launch(void* const* d_in, const int* in_sizes, int n_in,
                              void* d_out, int out_size) {
    const int*   x     = (const int*)  d_in[0];
    const float* embed = (const float*)d_in[1];
    const float* W_hx  = (const float*)d_in[2];
    const float* b_hx  = (const float*)d_in[3];
    const float* W_hh  = (const float*)d_in[4];
    const float* b_hh  = (const float*)d_in[5];
    const float* W_oh  = (const float*)d_in[6];
    const float* b_oh  = (const float*)d_in[7];
    float* out = (float*)d_out;

    cudaFuncSetAttribute(rnn_step_ws,
                         cudaFuncAttributeMaxDynamicSharedMemorySize, STEP_SMEM);

    precompute_T_kernel<<<dim3(H_ / 256, V_), 256>>>(embed, W_hx, b_hx);
    make_T2_kernel<<<(V_ * H_) / 256, 256>>>(b_hh);
    cvt_W_kernel<<<(H_ * H_) / 256, 256>>>(W_hh);
    init_h_kernel<<<(B_ * H_) / 256, 256>>>(x);

    dim3 grid(H_ / BN, B_ / BM);   // (16, 8) = 128 CTAs
    for (int t = 1; t < S_; t++) {
        int parity = (t - 1) & 1;
        rnn_step_ws<<<grid, NTHR, STEP_SMEM>>>(parity, x, t);
    }

    output_softmax_kernel<<<B_, 256>>>(W_oh, b_oh, out);
}